// round 13
// baseline (speedup 1.0000x reference)
#include <cuda_runtime.h>
#include <cuda_fp16.h>
#include <stdint.h>
#include <math.h>

#define NR 8192
#define DD 512

// ---------------- scratch (__device__ globals; no allocs allowed) ----------------
__device__ __align__(128) __half g_xh[(size_t)NR * DD];
__device__ __align__(128) __half g_wt[3][(size_t)DD * DD];   // W^T fp16; rows concat = B[1536][512]
__device__ __align__(128) __half g_qk[(size_t)NR * 1024];    // q (cols 0-511) | k (cols 512-1023)
__device__ __align__(128) __half g_vt[(size_t)DD * NR];      // v^T
__device__ __align__(128) __half g_E [(size_t)NR * NR];      // 128 MB, stores E * 2^-16
__device__ float g_rowsum[NR];                               // also scaled by 2^-16

// ---------------- helpers ----------------
__device__ __forceinline__ uint32_t smem_u32(const void* p) {
    uint32_t a;
    asm("{ .reg .u64 t; cvta.to.shared.u64 t, %1; cvt.u32.u64 %0, t; }" : "=r"(a) : "l"(p));
    return a;
}
__device__ __forceinline__ void ldsm4(uint32_t r[4], uint32_t a) {
    asm volatile("ldmatrix.sync.aligned.m8n8.x4.shared.b16 {%0,%1,%2,%3}, [%4];"
                 : "=r"(r[0]), "=r"(r[1]), "=r"(r[2]), "=r"(r[3]) : "r"(a));
}
__device__ __forceinline__ void mma16816(float d[4], const uint32_t a[4], const uint32_t b[2]) {
    asm volatile("mma.sync.aligned.m16n8k16.row.col.f32.f16.f16.f32 "
                 "{%0,%1,%2,%3}, {%4,%5,%6,%7}, {%8,%9}, {%0,%1,%2,%3};"
                 : "+f"(d[0]), "+f"(d[1]), "+f"(d[2]), "+f"(d[3])
                 : "r"(a[0]), "r"(a[1]), "r"(a[2]), "r"(a[3]), "r"(b[0]), "r"(b[1]));
}
__device__ __forceinline__ void cp16(uint32_t saddr, const void* gaddr) {
    asm volatile("cp.async.cg.shared.global [%0], [%1], 16;" :: "r"(saddr), "l"(gaddr));
}
#define CP_COMMIT() asm volatile("cp.async.commit_group;" ::: "memory")
#define CP_WAIT1()  asm volatile("cp.async.wait_group 1;" ::: "memory")

// 2^t, t in [-16.5, ~14], magic-number split + deg-4 poly (err ~4e-5 rel).
__device__ __forceinline__ float exp2_fast(float t) {
    const float MAGIC = 12582912.0f;             // 2^23 + 2^22
    float r = t + MAGIC;
    float f = t - (r - MAGIC);
    float p = 0.009618129f;
    p = fmaf(p, f, 0.05550411f);
    p = fmaf(p, f, 0.2402265f);
    p = fmaf(p, f, 0.6931472f);
    p = fmaf(p, f, 1.0f);
    float es = __int_as_float((int)((__float_as_int(r) + 0xB4C0007Fu) << 23));
    return es * p;
}

// ---------------- prep kernels ----------------
__global__ void conv_x_k(const float4* __restrict__ x) {
    size_t i = (size_t)blockIdx.x * 256 + threadIdx.x;
    if (i < NR) g_rowsum[i] = 0.0f;
    float4 v = x[i];
    __half2* H = (__half2*)g_xh;
    H[2 * i]     = __floats2half2_rn(v.x, v.y);
    H[2 * i + 1] = __floats2half2_rn(v.z, v.w);
}

__global__ void trans_w_k(const float* __restrict__ W0, const float* __restrict__ W1,
                          const float* __restrict__ W2) {
    __shared__ float t[32][33];
    const float* W = (blockIdx.z == 0) ? W0 : (blockIdx.z == 1) ? W1 : W2;
    __half* T = g_wt[blockIdx.z];
    int tx = threadIdx.x, ty = threadIdx.y;
    int xi = blockIdx.x * 32 + tx, yi = blockIdx.y * 32 + ty;
    #pragma unroll
    for (int i = 0; i < 32; i += 8) t[ty + i][tx] = W[(size_t)(yi + i) * DD + xi];
    __syncthreads();
    int xo = blockIdx.y * 32 + tx, yo = blockIdx.x * 32 + ty;
    #pragma unroll
    for (int i = 0; i < 32; i += 8)
        T[(size_t)(yo + i) * DD + xo] = __float2half_rn(t[tx][ty + i]);
}

// ============ mma.sync GEMM (256 thr, block 128x128): EPI 0 qkv, EPI 2 dot ==============
// EPI 0: abs -> fp16; gcol<1024 -> Ch (q|k row-major); else v^T via smem-staged transpose
// EPI 2: exp2(acc*scale - 16) -> fp16 Ch (ldc) + rowsum atomics
template<int EPI>
__global__ __launch_bounds__(256, 2)
void mma_gemm(const __half* __restrict__ A, int lda,
              const __half* __restrict__ B, int ldb,
              int K, int ldc,
              __half* __restrict__ Ch, __half* __restrict__ Ch2,
              float* __restrict__ rsum, float scale)
{
    constexpr int NS = 3;
    constexpr uint32_t TILE = 16384u;            // 128 x 128 B
    constexpr uint32_t STAGE = 2u * TILE;
    extern __shared__ char dyn[];
    __shared__ float red[128][4];

    const int tid = threadIdx.x;
    const int lane = tid & 31, wid = tid >> 5;
    const int wm = wid & 1, wn = wid >> 1;
    const int m0 = blockIdx.y * 128, n0 = blockIdx.x * 128;
    const uint32_t sbase = smem_u32(dyn);

    const int su = tid & 7;
    const int sr = tid >> 3;                     // 0..31
    const uint32_t soff = sr * 128 + ((su ^ (sr & 7)) << 4);

    uint32_t offA[4], offB[2];
    {
        const int ra = lane & 15, ua = lane >> 4;
        #pragma unroll
        for (int mi = 0; mi < 4; mi++) {
            int r = wm * 64 + mi * 16 + ra;
            offA[mi] = r * 128 + ((ua ^ (r & 7)) << 4);
        }
        const int rbv = ((lane >> 4) << 3) + (lane & 7), ub = (lane >> 3) & 1;
        #pragma unroll
        for (int np = 0; np < 2; np++) {
            int r = wn * 32 + np * 16 + rbv;
            offB[np] = TILE + r * 128 + ((ub ^ (r & 7)) << 4);
        }
    }

    float acc[4][4][4];
    #pragma unroll
    for (int a = 0; a < 4; a++)
        #pragma unroll
        for (int b = 0; b < 4; b++)
            #pragma unroll
            for (int c = 0; c < 4; c++) acc[a][b][c] = 0.0f;

    const int nkt = K >> 6;

    #pragma unroll
    for (int s = 0; s < NS - 1; s++) {
        const int kc = s * 64 + su * 8;
        const uint32_t db = sbase + (uint32_t)s * STAGE;
        #pragma unroll
        for (int j = 0; j < 4; j++) {
            cp16(db + soff + j * 4096u,        A + (size_t)(m0 + sr + 32 * j) * lda + kc);
            cp16(db + TILE + soff + j * 4096u, B + (size_t)(n0 + sr + 32 * j) * ldb + kc);
        }
        CP_COMMIT();
    }

    int stage = 0;
    for (int kt = 0; kt < nkt; kt++) {
        CP_WAIT1();
        __syncthreads();

        const uint32_t bb = sbase + (uint32_t)stage * STAGE;
        #pragma unroll
        for (int ks = 0; ks < 4; ks++) {
            const uint32_t kx = (uint32_t)ks << 5;
            uint32_t ah[4][4];
            #pragma unroll
            for (int mi = 0; mi < 4; mi++) ldsm4(ah[mi], bb + (offA[mi] ^ kx));
            uint32_t bh[2][4];
            #pragma unroll
            for (int np = 0; np < 2; np++) ldsm4(bh[np], bb + (offB[np] ^ kx));
            #pragma unroll
            for (int mi = 0; mi < 4; mi++)
                #pragma unroll
                for (int ni = 0; ni < 4; ni++)
                    mma16816(acc[mi][ni], ah[mi], &bh[ni >> 1][(ni & 1) * 2]);
        }

        if (kt + NS - 1 < nkt) {
            const int ldst = (stage + NS - 1) % NS;
            const int kc = (kt + NS - 1) * 64 + su * 8;
            const uint32_t db = sbase + (uint32_t)ldst * STAGE;
            #pragma unroll
            for (int j = 0; j < 4; j++) {
                cp16(db + soff + j * 4096u,        A + (size_t)(m0 + sr + 32 * j) * lda + kc);
                cp16(db + TILE + soff + j * 4096u, B + (size_t)(n0 + sr + 32 * j) * ldb + kc);
            }
        }
        CP_COMMIT();
        stage = (stage + 1 < NS) ? stage + 1 : 0;
    }

    // -------- epilogue --------
    const int lr = lane >> 2;
    const int lc = (lane & 3) << 1;

    if (EPI == 0 && n0 >= 1024) {
        // v region: stage 128x128 tile transposed in smem, then coalesced write of v^T
        __syncthreads();                          // mainloop done reading dyn
        __half* sm = (__half*)dyn;                // [col][row], pitch 136 halves
        #pragma unroll
        for (int mi = 0; mi < 4; mi++)
            #pragma unroll
            for (int h = 0; h < 2; h++) {
                const int lrow = wm * 64 + mi * 16 + h * 8 + lr;
                #pragma unroll
                for (int ni = 0; ni < 4; ni++) {
                    const int c = wn * 32 + ni * 8 + lc;  // local col 0..127
                    sm[(c)     * 136 + lrow] = __float2half_rn(fabsf(acc[mi][ni][h * 2 + 0]));
                    sm[(c + 1) * 136 + lrow] = __float2half_rn(fabsf(acc[mi][ni][h * 2 + 1]));
                }
            }
        __syncthreads();
        const int vc = (n0 - 1024) + (tid >> 1);        // global v col 0..511
        const int r0 = (tid & 1) * 64;
        #pragma unroll
        for (int j = 0; j < 8; j++) {
            uint4 val = *(uint4*)(sm + (size_t)(tid >> 1) * 136 + r0 + j * 8);
            *(uint4*)(Ch2 + (size_t)vc * NR + m0 + r0 + j * 8) = val;
        }
        return;
    }

    #pragma unroll
    for (int mi = 0; mi < 4; mi++) {
        #pragma unroll
        for (int h = 0; h < 2; h++) {
            const int lrow = wm * 64 + mi * 16 + h * 8 + lr;
            const int grow = m0 + lrow;
            float part = 0.0f;
            #pragma unroll
            for (int ni = 0; ni < 4; ni++) {
                float v0 = acc[mi][ni][h * 2 + 0];
                float v1 = acc[mi][ni][h * 2 + 1];
                const int gcol = n0 + wn * 32 + ni * 8 + lc;
                if (EPI == 0) {
                    *(__half2*)(Ch + (size_t)grow * 1024 + gcol) =
                        __floats2half2_rn(fabsf(v0), fabsf(v1));
                } else {
                    float e0 = exp2_fast(fmaf(v0, scale, -16.0f));
                    float e1 = exp2_fast(fmaf(v1, scale, -16.0f));
                    part += e0 + e1;
                    *(__half2*)(Ch + (size_t)grow * ldc + gcol) = __floats2half2_rn(e0, e1);
                }
            }
            if (EPI == 2) {
                part += __shfl_xor_sync(0xffffffffu, part, 1);
                part += __shfl_xor_sync(0xffffffffu, part, 2);
                if ((lane & 3) == 0) red[lrow][wn] = part;
            }
        }
    }
    if (EPI == 2) {
        __syncthreads();
        if (tid < 128)
            atomicAdd(&rsum[m0 + tid],
                      red[tid][0] + red[tid][1] + red[tid][2] + red[tid][3]);
    }
}

// ============ Ev kernel: block 128m x 256n, 512 threads, 16 warps (2m x 8n) =============
// out[grow][gcol] = (E' @ v) / rowsum'. A=E (lda=NR), B=v^T (ldb=NR). Halves E re-reads.
__global__ __launch_bounds__(512, 1)
void mma_ev(const __half* __restrict__ A, const __half* __restrict__ B,
            float* __restrict__ Cf, const float* __restrict__ rsum)
{
    constexpr int NS = 3;
    constexpr uint32_t ATILE = 16384u;           // 128 x 128 B
    constexpr uint32_t BTILE = 32768u;           // 256 x 128 B
    constexpr uint32_t STAGE = ATILE + BTILE;    // 48 KB
    extern __shared__ char dyn[];

    const int tid = threadIdx.x;
    const int lane = tid & 31, wid = tid >> 5;
    const int wm = wid & 1, wn = wid >> 1;       // wn 0..7
    const int m0 = blockIdx.y * 128, n0 = blockIdx.x * 256;
    const uint32_t sbase = smem_u32(dyn);

    const int su = tid & 7;
    const int sr = tid >> 3;                     // 0..63
    const uint32_t soff = sr * 128 + ((su ^ (sr & 7)) << 4);

    uint32_t offA[4], offB[2];
    {
        const int ra = lane & 15, ua = lane >> 4;
        #pragma unroll
        for (int mi = 0; mi < 4; mi++) {
            int r = wm * 64 + mi * 16 + ra;
            offA[mi] = r * 128 + ((ua ^ (r & 7)) << 4);
        }
        const int rbv = ((lane >> 4) << 3) + (lane & 7), ub = (lane >> 3) & 1;
        #pragma unroll
        for (int np = 0; np < 2; np++) {
            int r = wn * 32 + np * 16 + rbv;     // 0..255
            offB[np] = ATILE + r * 128 + ((ub ^ (r & 7)) << 4);
        }
    }

    float acc[4][4][4];
    #pragma unroll
    for (int a = 0; a < 4; a++)
        #pragma unroll
        for (int b = 0; b < 4; b++)
            #pragma unroll
            for (int c = 0; c < 4; c++) acc[a][b][c] = 0.0f;

    const int nkt = NR >> 6;                     // 128 chunks

    #pragma unroll
    for (int s = 0; s < NS - 1; s++) {
        const int kc = s * 64 + su * 8;
        const uint32_t db = sbase + (uint32_t)s * STAGE;
        #pragma unroll
        for (int j = 0; j < 2; j++)
            cp16(db + soff + j * 8192u, A + (size_t)(m0 + sr + 64 * j) * NR + kc);
        #pragma unroll
        for (int j = 0; j < 4; j++)
            cp16(db + ATILE + soff + j * 8192u, B + (size_t)(n0 + sr + 64 * j) * NR + kc);
        CP_COMMIT();
    }

    int stage = 0;
    for (int kt = 0; kt < nkt; kt++) {
        CP_WAIT1();
        __syncthreads();

        const uint32_t bb = sbase + (uint32_t)stage * STAGE;
        #pragma unroll
        for (int ks = 0; ks < 4; ks++) {
            const uint32_t kx = (uint32_t)ks << 5;
            uint32_t ah[4][4];
            #pragma unroll
            for (int mi = 0; mi < 4; mi++) ldsm4(ah[mi], bb + (offA[mi] ^ kx));
            uint32_t bh[2][4];
            #pragma unroll
            for (int np = 0; np < 2; np++) ldsm4(bh[np], bb + (offB[np] ^ kx));
            #pragma unroll
            for (int mi = 0; mi < 4; mi++)
                #pragma unroll
                for (int ni = 0; ni < 4; ni++)
                    mma16816(acc[mi][ni], ah[mi], &bh[ni >> 1][(ni & 1) * 2]);
        }

        if (kt + NS - 1 < nkt) {
            const int ldst = (stage + NS - 1) % NS;
            const int kc = (kt + NS - 1) * 64 + su * 8;
            const uint32_t db = sbase + (uint32_t)ldst * STAGE;
            #pragma unroll
            for (int j = 0; j < 2; j++)
                cp16(db + soff + j * 8192u, A + (size_t)(m0 + sr + 64 * j) * NR + kc);
            #pragma unroll
            for (int j = 0; j < 4; j++)
                cp16(db + ATILE + soff + j * 8192u, B + (size_t)(n0 + sr + 64 * j) * NR + kc);
        }
        CP_COMMIT();
        stage = (stage + 1 < NS) ? stage + 1 : 0;
    }

    const int lr = lane >> 2;
    const int lc = (lane & 3) << 1;
    #pragma unroll
    for (int mi = 0; mi < 4; mi++) {
        #pragma unroll
        for (int h = 0; h < 2; h++) {
            const int grow = m0 + wm * 64 + mi * 16 + h * 8 + lr;
            const float invr = 1.0f / rsum[grow];
            #pragma unroll
            for (int ni = 0; ni < 4; ni++) {
                const int gcol = n0 + wn * 32 + ni * 8 + lc;
                *(float2*)(Cf + (size_t)grow * DD + gcol) =
                    make_float2(acc[mi][ni][h * 2] * invr, acc[mi][ni][h * 2 + 1] * invr);
            }
        }
    }
}

// ---------------- launch ----------------
extern "C" void kernel_launch(void* const* d_in, const int* in_sizes, int n_in,
                              void* d_out, int out_size)
{
    (void)in_sizes; (void)n_in; (void)out_size;
    const float* x  = (const float*)d_in[0];
    const float* W[3] = {(const float*)d_in[1], (const float*)d_in[2], (const float*)d_in[3]};
    float* out = (float*)d_out;

    __half *xh, *wt0, *qk, *vt, *E;
    float* rs;
    cudaGetSymbolAddress((void**)&xh,  g_xh);
    cudaGetSymbolAddress((void**)&wt0, g_wt);
    cudaGetSymbolAddress((void**)&qk,  g_qk);
    cudaGetSymbolAddress((void**)&vt,  g_vt);
    cudaGetSymbolAddress((void**)&E,   g_E);
    cudaGetSymbolAddress((void**)&rs,  g_rowsum);

    const int SM  = 3 * 2 * 16384;   // 96 KB
    const int SMW = 3 * 49152;       // 144 KB (Ev wide)
    cudaFuncSetAttribute(mma_gemm<0>, cudaFuncAttributeMaxDynamicSharedMemorySize, SM);
    cudaFuncSetAttribute(mma_gemm<2>, cudaFuncAttributeMaxDynamicSharedMemorySize, SM);
    cudaFuncSetAttribute(mma_ev,      cudaFuncAttributeMaxDynamicSharedMemorySize, SMW);

    const float SC2 = 0.06375869843f;       // log2(e)/sqrt(512)

    conv_x_k<<<(NR * DD / 4) / 256, 256>>>((const float4*)x);
    trans_w_k<<<dim3(16, 16, 3), dim3(32, 8)>>>(W[0], W[1], W[2]);

    // merged qkv: q|k -> g_qk row-major; v -> g_vt transposed (smem-staged, coalesced)
    mma_gemm<0><<<dim3(1536 / 128, NR / 128), dim3(256), SM>>>(
        xh, DD, wt0, DD, DD, 0, qk, vt, nullptr, 0.f);

    // E' = exp(q k^T / sqrt(d)) * 2^-16 (bias cancels in final divide), rowsum
    mma_gemm<2><<<dim3(NR / 128, NR / 128), dim3(256), SM>>>(
        qk, 1024, qk + 512, 1024, DD, NR, E, nullptr, rs, SC2);

    // out = (E' v) / rowsum' — wide 128x256 tiles, E re-read 2x instead of 4x
    mma_ev<<<dim3(DD / 256, NR / 128), dim3(512), SMW>>>(E, vt, out, rs);
}